// round 13
// baseline (speedup 1.0000x reference)
#include <cuda_runtime.h>
#include <cuda_fp16.h>
#include <math.h>
#include <stdint.h>

#define BATCH 512
#define DIMV  512
#define INSZ  1537
#define HV    1538
#define HP    1664          // padded h / in_sz (multiple of 128)

// GEMM tiling: CTA 64x128, BK=128, 3-stage cp.async, 1 barrier/window
#define BM 64
#define BN 128
#define BK 128
#define PITCH 272                 // 256B row + 16B pad (conflict-free ldmatrix)
#define ST_A (64 * PITCH)         // 17408
#define ST_B (128 * PITCH)        // 34816
#define STG  (ST_A + ST_B)        // 52224
#define SMEM_TOT (3 * STG)        // 156672

// ------------------------------------------------------------------
// scratch (__device__ globals; no allocations allowed)
// ------------------------------------------------------------------
__device__ __half g_a0[BATCH * HP];
__device__ __half g_hA[BATCH * HP];
__device__ __half g_hB[BATCH * HP];
__device__ __half g_SCh[2 * BATCH * DIMV];     // fp16 [sin; cos]
__device__ float  g_SC[2 * BATCH * DIMV];      // fp32 [sin; cos]
__device__ float  g_FS[2 * BATCH * DIMV];      // forcesum GEMM out
__device__ float  g_part[4 * BATCH * DIMV];    // W3 split-K4 partials
__device__ unsigned int g_bar;                 // global barrier counter

__device__ __half g_W0[HP * HP];
__device__ __half g_W1[HP * HP];
__device__ __half g_W2[HP * HP];
__device__ __half g_W3[DIMV * HP];
__device__ __half g_A[DIMV * DIMV];

// ------------------------------------------------------------------
// helpers
// ------------------------------------------------------------------
__device__ __forceinline__ uint32_t smem_u32(const void* p) {
    uint32_t a;
    asm("{ .reg .u64 t; cvta.to.shared.u64 t, %1; cvt.u32.u64 %0, t; }"
        : "=r"(a) : "l"(p));
    return a;
}

#define CP_ASYNC16(dst, src) \
    asm volatile("cp.async.cg.shared.global [%0], [%1], 16;" \
                 :: "r"(dst), "l"(src) : "memory")
#define CP_COMMIT() asm volatile("cp.async.commit_group;" ::: "memory")
#define CP_WAIT1()  asm volatile("cp.async.wait_group 1;" ::: "memory")

#define LDSM4(r, addr) \
    asm volatile("ldmatrix.sync.aligned.m8n8.x4.shared.b16 {%0,%1,%2,%3}, [%4];" \
                 : "=r"((r)[0]), "=r"((r)[1]), "=r"((r)[2]), "=r"((r)[3]) : "r"(addr))

#define MMA16816(d, a, b0, b1) \
    asm volatile("mma.sync.aligned.m16n8k16.row.col.f32.f16.f16.f32 " \
                 "{%0,%1,%2,%3}, {%4,%5,%6,%7}, {%8,%9}, {%0,%1,%2,%3};" \
                 : "+f"((d)[0]), "+f"((d)[1]), "+f"((d)[2]), "+f"((d)[3]) \
                 : "r"((a)[0]), "r"((a)[1]), "r"((a)[2]), "r"((a)[3]), \
                   "r"(b0), "r"(b1))

#define ZERO_ACC(acc) do { \
    _Pragma("unroll") for (int i = 0; i < 2; i++) \
        _Pragma("unroll") for (int j = 0; j < 4; j++) \
            _Pragma("unroll") for (int q = 0; q < 4; q++) (acc)[i][j][q] = 0.f; \
} while (0)

// ------------------------------------------------------------------
// GEMM core: acc += A[M,K]fp16 @ B[N,K]^T fp16 over K-chunks [cb, ce).
// 64x128 CTA tile, BK=128, 3-stage cp.async, ONE barrier per window.
// ------------------------------------------------------------------
__device__ __forceinline__ void gemm_core(
    uint32_t smbase, const __half* __restrict__ A, int lda,
    const __half* __restrict__ B, int ldb,
    int m0, int n0, int cb, int ce, float (&acc)[2][4][4]) {

    int tid = threadIdx.x, lane = tid & 31, wid = tid >> 5;
    int wm = wid >> 2, wn = wid & 3;

    auto load_stage = [&](int buf, int c) {
        uint32_t s = smbase + buf * STG;
        #pragma unroll
        for (int i = 0; i < 4; i++) {               // A: 64 rows x 16 chunks
            int idx = tid + i * 256;
            int row = idx >> 4, ch = idx & 15;
            CP_ASYNC16(s + row * PITCH + ch * 16,
                       A + (size_t)(m0 + row) * lda + c * BK + ch * 8);
        }
        #pragma unroll
        for (int i = 0; i < 8; i++) {               // B: 128 rows x 16 chunks
            int idx = tid + i * 256;
            int row = idx >> 4, ch = idx & 15;
            CP_ASYNC16(s + ST_A + row * PITCH + ch * 16,
                       B + (size_t)(n0 + row) * ldb + c * BK + ch * 8);
        }
    };

    load_stage(0, cb); CP_COMMIT();
    load_stage(1, cb + 1); CP_COMMIT();

    int a_r = lane & 15, a_c = (lane >> 4) << 3;
    int b_r = (lane & 7) + ((lane >> 4) << 3), b_c = ((lane >> 3) & 1) << 3;

    int buf = 0;
    for (int c = cb; c < ce; c++) {
        CP_WAIT1();
        __syncthreads();
        uint32_t s = smbase + buf * STG;

        #pragma unroll
        for (int kk = 0; kk < 8; kk++) {
            uint32_t af[2][4], bf[2][4];
            #pragma unroll
            for (int mi = 0; mi < 2; mi++) {
                uint32_t off = s + (uint32_t)((wm * 32 + mi * 16 + a_r) * PITCH + kk * 32 + a_c * 2);
                LDSM4(af[mi], off);
            }
            #pragma unroll
            for (int ni = 0; ni < 2; ni++) {
                uint32_t off = s + ST_A + (uint32_t)((wn * 32 + ni * 16 + b_r) * PITCH + kk * 32 + b_c * 2);
                LDSM4(bf[ni], off);
            }
            #pragma unroll
            for (int mi = 0; mi < 2; mi++)
                #pragma unroll
                for (int nj = 0; nj < 4; nj++) {
                    uint32_t* bb = &bf[nj >> 1][(nj & 1) * 2];
                    MMA16816(acc[mi][nj], af[mi], bb[0], bb[1]);
                }
        }
        if (c + 2 < ce) {
            int nbuf = buf + 2; if (nbuf >= 3) nbuf -= 3;
            load_stage(nbuf, c + 2);
        }
        CP_COMMIT();
        if (++buf == 3) buf = 0;
    }
}

// ------------------------------------------------------------------
// epilogues
// ------------------------------------------------------------------
__device__ __forceinline__ void epi_tanh_f16(
    float (&acc)[2][4][4], const float* __restrict__ bias,
    __half* __restrict__ C, int m0, int n0) {
    int tid = threadIdx.x, lane = tid & 31, wid = tid >> 5;
    int wm = wid >> 2, wn = wid & 3;
    #pragma unroll
    for (int mi = 0; mi < 2; mi++)
        #pragma unroll
        for (int nj = 0; nj < 4; nj++) {
            float* d = acc[mi][nj];
            int row = m0 + wm * 32 + mi * 16 + (lane >> 2);
            int col = n0 + wn * 32 + nj * 8 + (lane & 3) * 2;
            float bb0 = (col < HV) ? bias[col] : 0.f;
            float bb1 = (col + 1 < HV) ? bias[col + 1] : 0.f;
            float v0 = tanhf(d[0] + bb0), v1 = tanhf(d[1] + bb1);
            float v2 = tanhf(d[2] + bb0), v3 = tanhf(d[3] + bb1);
            __half2 h0 = {__float2half_rn(v0), __float2half_rn(v1)};
            __half2 h1 = {__float2half_rn(v2), __float2half_rn(v3)};
            *reinterpret_cast<uint32_t*>(C + (size_t)row * HP + col) = *(uint32_t*)&h0;
            *reinterpret_cast<uint32_t*>(C + (size_t)(row + 8) * HP + col) = *(uint32_t*)&h1;
        }
}

__device__ __forceinline__ void epi_f32(
    float (&acc)[2][4][4], float* __restrict__ out, int ldc, int m0, int n0) {
    int tid = threadIdx.x, lane = tid & 31, wid = tid >> 5;
    int wm = wid >> 2, wn = wid & 3;
    #pragma unroll
    for (int mi = 0; mi < 2; mi++)
        #pragma unroll
        for (int nj = 0; nj < 4; nj++) {
            float* d = acc[mi][nj];
            int row = m0 + wm * 32 + mi * 16 + (lane >> 2);
            int col = n0 + wn * 32 + nj * 8 + (lane & 3) * 2;
            float2 u0 = {d[0], d[1]}, u1 = {d[2], d[3]};
            *reinterpret_cast<float2*>(out + (size_t)row * ldc + col) = u0;
            *reinterpret_cast<float2*>(out + (size_t)(row + 8) * ldc + col) = u1;
        }
}

// ------------------------------------------------------------------
// 128x128 transpose-convert: dst[n][k] = fp16(src[k][n]), zero pad
// ------------------------------------------------------------------
__device__ void convert128(const float* __restrict__ src, __half* __restrict__ dh,
                           int K, int N, int kt, int nt, float* tile) {
    int tid = threadIdx.x;
    int k0 = kt * 128, n0 = nt * 128;
    #pragma unroll 4
    for (int l = 0; l < 64; l++) {
        int idx = tid + l * 256;
        int kr = idx >> 7, nc = idx & 127;
        int k = k0 + kr, n = n0 + nc;
        tile[kr * 129 + nc] = (k < K && n < N) ? src[(size_t)k * N + n] : 0.f;
    }
    __syncthreads();
    #pragma unroll 4
    for (int l = 0; l < 32; l++) {
        int idx = tid + l * 256;
        int n = idx >> 6, kq = idx & 63;
        float x0 = tile[(kq * 2) * 129 + n];
        float x1 = tile[(kq * 2 + 1) * 129 + n];
        __half2 h = {__float2half_rn(x0), __float2half_rn(x1)};
        *reinterpret_cast<uint32_t*>(dh + (size_t)(n0 + n) * HP + k0 + kq * 2) = *(uint32_t*)&h;
    }
    __syncthreads();
}

// ------------------------------------------------------------------
// convert0: W0 (676 64x64 tiles) | A fp16 (256) | prep (512); resets g_bar
// ------------------------------------------------------------------
__global__ __launch_bounds__(256)
void convert0(const float* __restrict__ W0, const float* __restrict__ A,
              const float* __restrict__ t, const float* __restrict__ y,
              const float* __restrict__ freqs) {
    int bid = blockIdx.x, tid = threadIdx.x;
    if (bid == 0 && tid == 0) g_bar = 0;

    if (bid >= 932) {                // prep: one block per batch row
        int b = bid - 932;
        float temb = t[0] - 1.0f;
        __half* row = g_a0 + (size_t)b * HP;
        for (int i = tid; i < DIMV; i += 256) {
            float yv = y[b * (DIMV + 1) + i];
            float s, c;
            sincosf(yv, &s, &c);
            float fq = freqs[b * DIMV + i];
            row[i] = __float2half_rn(c);
            row[DIMV + i] = __float2half_rn(s);
            row[2 * DIMV + 1 + i] = __float2half_rn(fq);
            g_SC[b * DIMV + i] = s;
            g_SC[(BATCH + b) * DIMV + i] = c;
            g_SCh[b * DIMV + i] = __float2half_rn(s);
            g_SCh[(BATCH + b) * DIMV + i] = __float2half_rn(c);
        }
        if (tid == 0) row[2 * DIMV] = __float2half_rn(temb);
        for (int i = INSZ + tid; i < HP; i += 256) row[i] = __ushort_as_half(0);
        return;
    }

    if (bid >= 676) {                // A: elementwise fp16, float4 vectorized
        int idx4 = (bid - 676) * 256 + tid;
        float4 v = reinterpret_cast<const float4*>(A)[idx4];
        __half2 h0 = {__float2half_rn(v.x), __float2half_rn(v.y)};
        __half2 h1 = {__float2half_rn(v.z), __float2half_rn(v.w)};
        uint2 w = {*(uint32_t*)&h0, *(uint32_t*)&h1};
        reinterpret_cast<uint2*>(g_A)[idx4] = w;
        return;
    }

    // W0 transpose-convert, 64x64 tiles (26 kt x 26 nt)
    int kt = bid % 26, nt = bid / 26;
    int k0 = kt * 64, n0 = nt * 64;
    __shared__ float tile[64][65];
    #pragma unroll
    for (int l = 0; l < 8; l++) {
        int idx = tid + l * 256;
        int kr = idx >> 5, cp = idx & 31;
        int k = k0 + kr, n = n0 + cp * 2;
        float2 v = {0.f, 0.f};
        if (k < INSZ) {
            if (n + 1 < HV) v = *reinterpret_cast<const float2*>(W0 + (size_t)k * HV + n);
            else if (n < HV) v.x = W0[(size_t)k * HV + n];
        }
        tile[kr][cp * 2] = v.x;
        tile[kr][cp * 2 + 1] = v.y;
    }
    __syncthreads();
    #pragma unroll
    for (int l = 0; l < 8; l++) {
        int idx = tid + l * 256;
        int n = idx >> 5, kq = idx & 31;
        __half2 h = {__float2half_rn(tile[kq * 2][n]), __float2half_rn(tile[kq * 2 + 1][n])};
        size_t o = (size_t)(n0 + n) * HP + k0 + kq * 2;
        *reinterpret_cast<uint32_t*>(g_W0 + o) = *(uint32_t*)&h;
    }
}

// ------------------------------------------------------------------
// global barrier (all CTAs co-resident: grid == #SMs, 1 CTA/SM)
// ------------------------------------------------------------------
__device__ __forceinline__ void global_barrier(unsigned int gen) {
    __syncthreads();
    if (threadIdx.x == 0) {
        __threadfence();
        unsigned int target = gen * gridDim.x;
        unsigned int arr = atomicAdd(&g_bar, 1u) + 1;
        if (arr < target) {
            while (atomicAdd(&g_bar, 0u) < target) { }
        }
        __threadfence();
    }
    __syncthreads();
}

// ------------------------------------------------------------------
// mega: persistent chain. blocks [0,104) run L0,L1,L2 GEMMs;
// helper blocks [104, grid) run forcesum + W1/W2/W3 conversion in the shadow.
// ------------------------------------------------------------------
__global__ __launch_bounds__(256)
void mega(const float* __restrict__ b0, const float* __restrict__ b1,
          const float* __restrict__ b2,
          const float* __restrict__ W1, const float* __restrict__ W2,
          const float* __restrict__ W3) {
    extern __shared__ __align__(16) char smraw[];
    uint32_t smbase = smem_u32(smraw);
    float* ftile = reinterpret_cast<float*>(smraw);
    int bid = blockIdx.x;
    int H = gridDim.x - 104;                 // helper count
    int j = bid - 104;

    float acc[2][4][4];

    // ---------------- phase 0: L0 || (forcesum + W1 convert) --------------
    if (bid < 104) {
        int m0 = (bid / 13) * BM, n0 = (bid % 13) * BN;
        ZERO_ACC(acc);
        gemm_core(smbase, g_a0, HP, g_W0, HP, m0, n0, 0, HP / BK, acc);
        epi_tanh_f16(acc, b0, g_hA, m0, n0);
    } else {
        for (int u = j; u < 64; u += H) {    // forcesum units
            int m0 = (u >> 2) * BM, n0 = (u & 3) * BN;
            ZERO_ACC(acc);
            gemm_core(smbase, g_SCh, DIMV, g_A, DIMV, m0, n0, 0, DIMV / BK, acc);
            epi_f32(acc, g_FS, DIMV, m0, n0);
        }
        for (int u = j; u < 169; u += H)     // W1 convert (13 kt x 13 nt)
            convert128(W1, g_W1, HV, HV, u % 13, u / 13, ftile);
    }
    global_barrier(1);

    // ---------------- phase 1: L1 || W2 convert ---------------------------
    if (bid < 104) {
        int m0 = (bid / 13) * BM, n0 = (bid % 13) * BN;
        ZERO_ACC(acc);
        gemm_core(smbase, g_hA, HP, g_W1, HP, m0, n0, 0, HP / BK, acc);
        epi_tanh_f16(acc, b1, g_hB, m0, n0);
    } else {
        for (int u = j; u < 169; u += H)
            convert128(W2, g_W2, HV, HV, u % 13, u / 13, ftile);
    }
    global_barrier(2);

    // ---------------- phase 2: L2 || W3 convert ---------------------------
    if (bid < 104) {
        int m0 = (bid / 13) * BM, n0 = (bid % 13) * BN;
        ZERO_ACC(acc);
        gemm_core(smbase, g_hB, HP, g_W2, HP, m0, n0, 0, HP / BK, acc);
        epi_tanh_f16(acc, b2, g_hA, m0, n0);
    } else {
        for (int u = j; u < 52; u += H)      // W3: 13 kt x 4 nt
            convert128(W3, g_W3, HV, DIMV, u % 13, u / 13, ftile);
    }
}

// ------------------------------------------------------------------
// tail: W3 split-K4 partials, grid 128
// ------------------------------------------------------------------
__global__ __launch_bounds__(256)
void tail_gemm(const __half* __restrict__ h2) {
    extern __shared__ __align__(16) char smraw[];
    uint32_t smbase = smem_u32(smraw);
    int b = blockIdx.x;
    int sp = b >> 5, r = b & 31;
    int m0 = (r >> 2) * BM, n0 = (r & 3) * BN;
    const int cbs[5] = {0, 4, 7, 10, 13};
    float acc[2][4][4];
    ZERO_ACC(acc);
    gemm_core(smbase, h2, HP, g_W3, HP, m0, n0, cbs[sp], cbs[sp + 1], acc);
    epi_f32(acc, g_part + (size_t)sp * BATCH * DIMV, DIMV, m0, n0);
}

// ------------------------------------------------------------------
// final: cf = p0+p1+p2+p3 + b3; force = cf*(c*FSs - s*FSc)/dim + freqs;
// f1 = rowsum(cf^2)
// ------------------------------------------------------------------
__global__ __launch_bounds__(256)
void final_kernel(const float* __restrict__ freqs, const float* __restrict__ b3,
                  float* __restrict__ out) {
    int b = blockIdx.x, tid = threadIdx.x;
    float sum = 0.f;
    for (int i = tid; i < DIMV; i += 256) {
        size_t o = (size_t)b * DIMV + i;
        float cf = g_part[o] + g_part[BATCH * DIMV + o]
                 + g_part[2 * BATCH * DIMV + o] + g_part[3 * BATCH * DIMV + o] + b3[i];
        float s = g_SC[o];
        float c = g_SC[BATCH * DIMV + o];
        float fs = c * g_FS[o] - s * g_FS[BATCH * DIMV + o];
        out[b * (DIMV + 1) + i] = cf * fs * (1.0f / DIMV) + freqs[o];
        sum += cf * cf;
    }
    __shared__ float red[8];
    #pragma unroll
    for (int o = 16; o; o >>= 1) sum += __shfl_down_sync(0xffffffffu, sum, o);
    if ((tid & 31) == 0) red[tid >> 5] = sum;
    __syncthreads();
    if (tid < 8) {
        float v = red[tid];
        #pragma unroll
        for (int o = 4; o; o >>= 1) v += __shfl_down_sync(0xffu, v, o);
        if (tid == 0) out[b * (DIMV + 1) + DIMV] = v;
    }
}

// ------------------------------------------------------------------
// launch
// ------------------------------------------------------------------
extern "C" void kernel_launch(void* const* d_in, const int* in_sizes, int n_in,
                              void* d_out, int out_size) {
    const float* t     = (const float*)d_in[0];
    const float* y     = (const float*)d_in[1];
    const float* freqs = (const float*)d_in[2];
    const float* A     = (const float*)d_in[3];
    const float* W0    = (const float*)d_in[4];
    const float* b0    = (const float*)d_in[5];
    const float* W1    = (const float*)d_in[6];
    const float* b1    = (const float*)d_in[7];
    const float* W2    = (const float*)d_in[8];
    const float* b2    = (const float*)d_in[9];
    const float* W3    = (const float*)d_in[10];
    const float* b3    = (const float*)d_in[11];
    float* out = (float*)d_out;

    __half* p_hA;
    cudaGetSymbolAddress((void**)&p_hA, g_hA);

    static int nsm = 0;
    if (nsm == 0) {
        cudaDeviceGetAttribute(&nsm, cudaDevAttrMultiProcessorCount, 0);
        if (nsm < 105) nsm = 105;           // need >= 1 helper CTA
        if (nsm > 148) nsm = 148;
        cudaFuncSetAttribute(mega,      cudaFuncAttributeMaxDynamicSharedMemorySize, SMEM_TOT);
        cudaFuncSetAttribute(tail_gemm, cudaFuncAttributeMaxDynamicSharedMemorySize, SMEM_TOT);
    }

    convert0<<<1444, 256>>>(W0, A, t, y, freqs);
    mega<<<nsm, 256, SMEM_TOT>>>(b0, b1, b2, W1, W2, W3);
    tail_gemm<<<128, 256, SMEM_TOT>>>(p_hA);
    final_kernel<<<BATCH, 256>>>(freqs, b3, out);
}

// round 14
// speedup vs baseline: 1.3396x; 1.3396x over previous
#include <cuda_runtime.h>
#include <cuda_fp16.h>
#include <math.h>
#include <stdint.h>

#define BATCH 512
#define DIMV  512
#define INSZ  1537
#define HV    1538
#define HP    1664          // padded h / in_sz (multiple of 128)

// GEMM tiling: CTA 64x128, BK=128, 3-stage cp.async, 1 barrier/window
#define BM 64
#define BN 128
#define BK 128
#define PITCH 272                 // 256B row + 16B pad (conflict-free ldmatrix)
#define ST_A (64 * PITCH)         // 17408
#define ST_B (128 * PITCH)        // 34816
#define STG  (ST_A + ST_B)        // 52224
#define SMEM_TOT (3 * STG)        // 156672

// ------------------------------------------------------------------
// scratch (__device__ globals; no allocations allowed)
// ------------------------------------------------------------------
__device__ __half g_a0[BATCH * HP];
__device__ __half g_hA[BATCH * HP];
__device__ __half g_hB[BATCH * HP];
__device__ __half g_SCh[2 * BATCH * DIMV];     // fp16 [sin; cos]
__device__ float  g_SC[2 * BATCH * DIMV];      // fp32 [sin; cos]
__device__ float  g_FS[2 * BATCH * DIMV];      // forcesum GEMM out
__device__ float  g_part[4 * BATCH * DIMV];    // W3 split-K4 partials

__device__ __half g_W0[HP * HP];
__device__ __half g_W1[HP * HP];
__device__ __half g_W2[HP * HP];
__device__ __half g_W3[DIMV * HP];
__device__ __half g_A[DIMV * DIMV];

// ------------------------------------------------------------------
// helpers
// ------------------------------------------------------------------
__device__ __forceinline__ uint32_t smem_u32(const void* p) {
    uint32_t a;
    asm("{ .reg .u64 t; cvta.to.shared.u64 t, %1; cvt.u32.u64 %0, t; }"
        : "=r"(a) : "l"(p));
    return a;
}

#define CP_ASYNC16(dst, src) \
    asm volatile("cp.async.cg.shared.global [%0], [%1], 16;" \
                 :: "r"(dst), "l"(src) : "memory")
#define CP_COMMIT() asm volatile("cp.async.commit_group;" ::: "memory")
#define CP_WAIT1()  asm volatile("cp.async.wait_group 1;" ::: "memory")

#define LDSM4(r, addr) \
    asm volatile("ldmatrix.sync.aligned.m8n8.x4.shared.b16 {%0,%1,%2,%3}, [%4];" \
                 : "=r"((r)[0]), "=r"((r)[1]), "=r"((r)[2]), "=r"((r)[3]) : "r"(addr))

#define MMA16816(d, a, b0, b1) \
    asm volatile("mma.sync.aligned.m16n8k16.row.col.f32.f16.f16.f32 " \
                 "{%0,%1,%2,%3}, {%4,%5,%6,%7}, {%8,%9}, {%0,%1,%2,%3};" \
                 : "+f"((d)[0]), "+f"((d)[1]), "+f"((d)[2]), "+f"((d)[3]) \
                 : "r"((a)[0]), "r"((a)[1]), "r"((a)[2]), "r"((a)[3]), \
                   "r"(b0), "r"(b1))

#define ZERO_ACC(acc) do { \
    _Pragma("unroll") for (int i = 0; i < 2; i++) \
        _Pragma("unroll") for (int j = 0; j < 4; j++) \
            _Pragma("unroll") for (int q = 0; q < 4; q++) (acc)[i][j][q] = 0.f; \
} while (0)

// ------------------------------------------------------------------
// fused prep + conversion.
// blocks [0,676) W0 | [676,1352) W1 | [1352,2028) W2 | [2028,2236) W3
//        [2236,2492) A elementwise | [2492,3004) prep (per batch row)
// ------------------------------------------------------------------
__global__ __launch_bounds__(256)
void convert_all(const float* __restrict__ W0, const float* __restrict__ W1,
                 const float* __restrict__ W2, const float* __restrict__ W3,
                 const float* __restrict__ A,
                 const float* __restrict__ t, const float* __restrict__ y,
                 const float* __restrict__ freqs) {
    int bid = blockIdx.x, tid = threadIdx.x;

    if (bid >= 2492) {               // prep: one block per batch row
        int b = bid - 2492;
        float temb = t[0] - 1.0f;
        __half* row = g_a0 + (size_t)b * HP;
        for (int i = tid; i < DIMV; i += 256) {
            float yv = y[b * (DIMV + 1) + i];
            float s, c;
            sincosf(yv, &s, &c);
            float fq = freqs[b * DIMV + i];
            row[i] = __float2half_rn(c);
            row[DIMV + i] = __float2half_rn(s);
            row[2 * DIMV + 1 + i] = __float2half_rn(fq);
            g_SC[b * DIMV + i] = s;
            g_SC[(BATCH + b) * DIMV + i] = c;
            g_SCh[b * DIMV + i] = __float2half_rn(s);
            g_SCh[(BATCH + b) * DIMV + i] = __float2half_rn(c);
        }
        if (tid == 0) row[2 * DIMV] = __float2half_rn(temb);
        for (int i = INSZ + tid; i < HP; i += 256) row[i] = __ushort_as_half(0);
        return;
    }

    if (bid >= 2236) {               // A: elementwise fp16, float4 vectorized
        int idx4 = (bid - 2236) * 256 + tid;
        float4 v = reinterpret_cast<const float4*>(A)[idx4];
        __half2 h0 = {__float2half_rn(v.x), __float2half_rn(v.y)};
        __half2 h1 = {__float2half_rn(v.z), __float2half_rn(v.w)};
        uint2 w = {*(uint32_t*)&h0, *(uint32_t*)&h1};
        reinterpret_cast<uint2*>(g_A)[idx4] = w;
        return;
    }

    const float* src;
    __half* dh;
    int K, N, tt;
    if (bid < 676)       { src = W0; dh = g_W0; K = INSZ; N = HV;   tt = bid;        }
    else if (bid < 1352) { src = W1; dh = g_W1; K = HV;   N = HV;   tt = bid - 676;  }
    else if (bid < 2028) { src = W2; dh = g_W2; K = HV;   N = HV;   tt = bid - 1352; }
    else                 { src = W3; dh = g_W3; K = HV;   N = DIMV; tt = bid - 2028; }
    int kt = tt % 26, nt = tt / 26;
    int k0 = kt * 64, n0 = nt * 64;

    __shared__ float tile[64][65];
    #pragma unroll
    for (int l = 0; l < 8; l++) {
        int idx = tid + l * 256;
        int kr = idx >> 5, cp = idx & 31;
        int k = k0 + kr, n = n0 + cp * 2;
        float2 v = {0.f, 0.f};
        if (k < K) {
            if (n + 1 < N) v = *reinterpret_cast<const float2*>(src + (size_t)k * N + n);
            else if (n < N) v.x = src[(size_t)k * N + n];
        }
        tile[kr][cp * 2] = v.x;
        tile[kr][cp * 2 + 1] = v.y;
    }
    __syncthreads();
    #pragma unroll
    for (int l = 0; l < 8; l++) {
        int idx = tid + l * 256;
        int n = idx >> 5, kq = idx & 31;
        __half2 h = {__float2half_rn(tile[kq * 2][n]), __float2half_rn(tile[kq * 2 + 1][n])};
        size_t o = (size_t)(n0 + n) * HP + k0 + kq * 2;
        *reinterpret_cast<uint32_t*>(dh + o) = *(uint32_t*)&h;
    }
}

// ------------------------------------------------------------------
// GEMM core: acc += A[M,K]fp16 @ B[N,K]^T fp16 over K-chunks [cb, ce).
// 64x128 CTA tile, BK=128, 3-stage cp.async, ONE barrier per window.
// ------------------------------------------------------------------
__device__ __forceinline__ void gemm_core(
    uint32_t smbase, const __half* __restrict__ A, int lda,
    const __half* __restrict__ B, int ldb,
    int m0, int n0, int cb, int ce, float (&acc)[2][4][4]) {

    int tid = threadIdx.x, lane = tid & 31, wid = tid >> 5;
    int wm = wid >> 2, wn = wid & 3;

    auto load_stage = [&](int buf, int c) {
        uint32_t s = smbase + buf * STG;
        #pragma unroll
        for (int i = 0; i < 4; i++) {               // A: 64 rows x 16 chunks
            int idx = tid + i * 256;
            int row = idx >> 4, ch = idx & 15;
            CP_ASYNC16(s + row * PITCH + ch * 16,
                       A + (size_t)(m0 + row) * lda + c * BK + ch * 8);
        }
        #pragma unroll
        for (int i = 0; i < 8; i++) {               // B: 128 rows x 16 chunks
            int idx = tid + i * 256;
            int row = idx >> 4, ch = idx & 15;
            CP_ASYNC16(s + ST_A + row * PITCH + ch * 16,
                       B + (size_t)(n0 + row) * ldb + c * BK + ch * 8);
        }
    };

    load_stage(0, cb); CP_COMMIT();
    load_stage(1, cb + 1); CP_COMMIT();

    int a_r = lane & 15, a_c = (lane >> 4) << 3;
    int b_r = (lane & 7) + ((lane >> 4) << 3), b_c = ((lane >> 3) & 1) << 3;

    int buf = 0;
    for (int c = cb; c < ce; c++) {
        CP_WAIT1();
        __syncthreads();
        uint32_t s = smbase + buf * STG;

        #pragma unroll
        for (int kk = 0; kk < 8; kk++) {
            uint32_t af[2][4], bf[2][4];
            #pragma unroll
            for (int mi = 0; mi < 2; mi++) {
                uint32_t off = s + (uint32_t)((wm * 32 + mi * 16 + a_r) * PITCH + kk * 32 + a_c * 2);
                LDSM4(af[mi], off);
            }
            #pragma unroll
            for (int ni = 0; ni < 2; ni++) {
                uint32_t off = s + ST_A + (uint32_t)((wn * 32 + ni * 16 + b_r) * PITCH + kk * 32 + b_c * 2);
                LDSM4(bf[ni], off);
            }
            #pragma unroll
            for (int mi = 0; mi < 2; mi++)
                #pragma unroll
                for (int nj = 0; nj < 4; nj++) {
                    uint32_t* bb = &bf[nj >> 1][(nj & 1) * 2];
                    MMA16816(acc[mi][nj], af[mi], bb[0], bb[1]);
                }
        }
        if (c + 2 < ce) {
            int nbuf = buf + 2; if (nbuf >= 3) nbuf -= 3;
            load_stage(nbuf, c + 2);
        }
        CP_COMMIT();
        if (++buf == 3) buf = 0;
    }
}

// ------------------------------------------------------------------
// epilogues
// ------------------------------------------------------------------
__device__ __forceinline__ void epi_tanh_f16(
    float (&acc)[2][4][4], const float* __restrict__ bias,
    __half* __restrict__ C, int m0, int n0) {
    int tid = threadIdx.x, lane = tid & 31, wid = tid >> 5;
    int wm = wid >> 2, wn = wid & 3;
    #pragma unroll
    for (int mi = 0; mi < 2; mi++)
        #pragma unroll
        for (int nj = 0; nj < 4; nj++) {
            float* d = acc[mi][nj];
            int row = m0 + wm * 32 + mi * 16 + (lane >> 2);
            int col = n0 + wn * 32 + nj * 8 + (lane & 3) * 2;
            float bb0 = (col < HV) ? bias[col] : 0.f;
            float bb1 = (col + 1 < HV) ? bias[col + 1] : 0.f;
            float v0 = tanhf(d[0] + bb0), v1 = tanhf(d[1] + bb1);
            float v2 = tanhf(d[2] + bb0), v3 = tanhf(d[3] + bb1);
            __half2 h0 = {__float2half_rn(v0), __float2half_rn(v1)};
            __half2 h1 = {__float2half_rn(v2), __float2half_rn(v3)};
            *reinterpret_cast<uint32_t*>(C + (size_t)row * HP + col) = *(uint32_t*)&h0;
            *reinterpret_cast<uint32_t*>(C + (size_t)(row + 8) * HP + col) = *(uint32_t*)&h1;
        }
}

__device__ __forceinline__ void epi_f32(
    float (&acc)[2][4][4], float* __restrict__ out, int ldc, int m0, int n0) {
    int tid = threadIdx.x, lane = tid & 31, wid = tid >> 5;
    int wm = wid >> 2, wn = wid & 3;
    #pragma unroll
    for (int mi = 0; mi < 2; mi++)
        #pragma unroll
        for (int nj = 0; nj < 4; nj++) {
            float* d = acc[mi][nj];
            int row = m0 + wm * 32 + mi * 16 + (lane >> 2);
            int col = n0 + wn * 32 + nj * 8 + (lane & 3) * 2;
            float2 u0 = {d[0], d[1]}, u1 = {d[2], d[3]};
            *reinterpret_cast<float2*>(out + (size_t)row * ldc + col) = u0;
            *reinterpret_cast<float2*>(out + (size_t)(row + 8) * ldc + col) = u1;
        }
}

// ------------------------------------------------------------------
// hidden layer: C = fp16(tanh(A @ B^T + bias)), full K (13 windows)
// ------------------------------------------------------------------
__global__ __launch_bounds__(256)
void hidden_gemm(const __half* __restrict__ A, const __half* __restrict__ B,
                 const float* __restrict__ bias, __half* __restrict__ C) {
    extern __shared__ __align__(16) char smraw[];
    uint32_t smbase = smem_u32(smraw);
    int m0 = blockIdx.y * BM, n0 = blockIdx.x * BN;
    float acc[2][4][4];
    ZERO_ACC(acc);
    gemm_core(smbase, A, HP, B, HP, m0, n0, 0, HP / BK, acc);
    epi_tanh_f16(acc, bias, C, m0, n0);
}

// ------------------------------------------------------------------
// L2 + forcesum fused: blocks [0,104) = L2 GEMM; [104,148) = FS helpers
// (FS is independent fp16 GEMM work; fits in idle-SM shadow: 403 < 902 µs·SM)
// ------------------------------------------------------------------
__global__ __launch_bounds__(256)
void l2fs_gemm(const __half* __restrict__ A, const __half* __restrict__ B,
               const float* __restrict__ bias, __half* __restrict__ C) {
    extern __shared__ __align__(16) char smraw[];
    uint32_t smbase = smem_u32(smraw);
    int bid = blockIdx.x;
    float acc[2][4][4];

    if (bid < 104) {
        int m0 = (bid / 13) * BM, n0 = (bid % 13) * BN;
        ZERO_ACC(acc);
        gemm_core(smbase, A, HP, B, HP, m0, n0, 0, HP / BK, acc);
        epi_tanh_f16(acc, bias, C, m0, n0);
    } else {
        int H = gridDim.x - 104;
        for (int u = bid - 104; u < 64; u += H) {
            int m0 = (u >> 2) * BM, n0 = (u & 3) * BN;
            ZERO_ACC(acc);
            gemm_core(smbase, g_SCh, DIMV, g_A, DIMV, m0, n0, 0, DIMV / BK, acc);
            epi_f32(acc, g_FS, DIMV, m0, n0);
        }
    }
}

// ------------------------------------------------------------------
// tail: W3 split-K4 partials, grid 128
// ------------------------------------------------------------------
__global__ __launch_bounds__(256)
void tail_gemm(const __half* __restrict__ h2) {
    extern __shared__ __align__(16) char smraw[];
    uint32_t smbase = smem_u32(smraw);
    int b = blockIdx.x;
    int sp = b >> 5, r = b & 31;
    int m0 = (r >> 2) * BM, n0 = (r & 3) * BN;
    const int cbs[5] = {0, 4, 7, 10, 13};
    float acc[2][4][4];
    ZERO_ACC(acc);
    gemm_core(smbase, h2, HP, g_W3, HP, m0, n0, cbs[sp], cbs[sp + 1], acc);
    epi_f32(acc, g_part + (size_t)sp * BATCH * DIMV, DIMV, m0, n0);
}

// ------------------------------------------------------------------
// final: cf = p0+p1+p2+p3 + b3; force = cf*(c*FSs - s*FSc)/dim + freqs;
// f1 = rowsum(cf^2)
// ------------------------------------------------------------------
__global__ __launch_bounds__(256)
void final_kernel(const float* __restrict__ freqs, const float* __restrict__ b3,
                  float* __restrict__ out) {
    int b = blockIdx.x, tid = threadIdx.x;
    float sum = 0.f;
    for (int i = tid; i < DIMV; i += 256) {
        size_t o = (size_t)b * DIMV + i;
        float cf = g_part[o] + g_part[BATCH * DIMV + o]
                 + g_part[2 * BATCH * DIMV + o] + g_part[3 * BATCH * DIMV + o] + b3[i];
        float s = g_SC[o];
        float c = g_SC[BATCH * DIMV + o];
        float fs = c * g_FS[o] - s * g_FS[BATCH * DIMV + o];
        out[b * (DIMV + 1) + i] = cf * fs * (1.0f / DIMV) + freqs[o];
        sum += cf * cf;
    }
    __shared__ float red[8];
    #pragma unroll
    for (int o = 16; o; o >>= 1) sum += __shfl_down_sync(0xffffffffu, sum, o);
    if ((tid & 31) == 0) red[tid >> 5] = sum;
    __syncthreads();
    if (tid < 8) {
        float v = red[tid];
        #pragma unroll
        for (int o = 4; o; o >>= 1) v += __shfl_down_sync(0xffu, v, o);
        if (tid == 0) out[b * (DIMV + 1) + DIMV] = v;
    }
}

// ------------------------------------------------------------------
// launch
// ------------------------------------------------------------------
extern "C" void kernel_launch(void* const* d_in, const int* in_sizes, int n_in,
                              void* d_out, int out_size) {
    const float* t     = (const float*)d_in[0];
    const float* y     = (const float*)d_in[1];
    const float* freqs = (const float*)d_in[2];
    const float* A     = (const float*)d_in[3];
    const float* W0    = (const float*)d_in[4];
    const float* b0    = (const float*)d_in[5];
    const float* W1    = (const float*)d_in[6];
    const float* b1    = (const float*)d_in[7];
    const float* W2    = (const float*)d_in[8];
    const float* b2    = (const float*)d_in[9];
    const float* W3    = (const float*)d_in[10];
    const float* b3    = (const float*)d_in[11];
    float* out = (float*)d_out;

    __half *p_a0, *p_hA, *p_hB, *p_W0, *p_W1, *p_W2;
    cudaGetSymbolAddress((void**)&p_a0, g_a0);
    cudaGetSymbolAddress((void**)&p_hA, g_hA);
    cudaGetSymbolAddress((void**)&p_hB, g_hB);
    cudaGetSymbolAddress((void**)&p_W0, g_W0);
    cudaGetSymbolAddress((void**)&p_W1, g_W1);
    cudaGetSymbolAddress((void**)&p_W2, g_W2);

    static int nsm = 0;
    if (nsm == 0) {
        cudaDeviceGetAttribute(&nsm, cudaDevAttrMultiProcessorCount, 0);
        if (nsm < 105) nsm = 105;
        if (nsm > 148) nsm = 148;
        cudaFuncSetAttribute(hidden_gemm, cudaFuncAttributeMaxDynamicSharedMemorySize, SMEM_TOT);
        cudaFuncSetAttribute(l2fs_gemm,   cudaFuncAttributeMaxDynamicSharedMemorySize, SMEM_TOT);
        cudaFuncSetAttribute(tail_gemm,   cudaFuncAttributeMaxDynamicSharedMemorySize, SMEM_TOT);
    }

    convert_all<<<3004, 256>>>(W0, W1, W2, W3, A, t, y, freqs);

    dim3 gridH(HP / BN, BATCH / BM);   // (13, 8) = 104 CTAs
    hidden_gemm<<<gridH, 256, SMEM_TOT>>>(p_a0, p_W0, b0, p_hA);
    hidden_gemm<<<gridH, 256, SMEM_TOT>>>(p_hA, p_W1, b1, p_hB);
    l2fs_gemm<<<nsm, 256, SMEM_TOT>>>(p_hB, p_W2, b2, p_hA);

    tail_gemm<<<128, 256, SMEM_TOT>>>(p_hA);

    final_kernel<<<BATCH, 256>>>(freqs, b3, out);
}